// round 16
// baseline (speedup 1.0000x reference)
#include <cuda_runtime.h>
#include <cuda_bf16.h>
#include <cstdint>

#define BB 32
#define SS 512
#define DD 768
#define SQ 511
#define NROWS (BB*SQ)
#define NEG_INF __int_as_float(0xff800000)

#define KCH 12             // 12 k-chunks of 64 over D=768
#define CH_ST 24           // stored chunks per (b,tile): hi[0..11], mid[12..23]
#define TAU 1e-4f
#define NTILES (16*BB)     // 512 output tiles

// prepped tiles: [b][tile(0..3)][chunk(0..23)][128 rows x 64 bf16, swizzled]
__device__ uint4 g_Apre[(size_t)BB * 4 * CH_ST * 1024];
__device__ uint4 g_Bpre[(size_t)BB * 4 * CH_ST * 1024];
__device__ float g_invn[NROWS];
__device__ float g_pv1[NROWS * 4];
__device__ int   g_pj1[NROWS * 4];
__device__ float g_pv2[NROWS * 4];
__device__ int   g_idx[NROWS];
__device__ int   g_queue[NROWS];
__device__ int   g_qcnt;
__device__ float g_txt_sum;
__device__ float g_img_sum;
__device__ int   g_valid;

__device__ __forceinline__ uint32_t smem_u32(const void* p) {
    uint32_t a;
    asm("{ .reg .u64 t; cvta.to.shared.u64 t, %1; cvt.u32.u64 %0, t; }"
        : "=r"(a) : "l"(p));
    return a;
}

// ============================ init ============================

__global__ void k_init() {
    g_txt_sum = 0.f; g_img_sum = 0.f; g_valid = 0; g_qcnt = 0;
}

// ============================ prep helpers ============================

__device__ __forceinline__ uint4 pack8(const unsigned short* u) {
    uint4 v;
    v.x = (uint32_t)u[0] | ((uint32_t)u[1] << 16);
    v.y = (uint32_t)u[2] | ((uint32_t)u[3] << 16);
    v.z = (uint32_t)u[4] | ((uint32_t)u[5] << 16);
    v.w = (uint32_t)u[6] | ((uint32_t)u[7] << 16);
    return v;
}

__device__ __forceinline__ void split8(const float* x, uint4& vh, uint4& vm) {
    unsigned short h[8], m[8];
#pragma unroll
    for (int q = 0; q < 8; q++) {
        __nv_bfloat16 bh = __float2bfloat16(x[q]);
        float r1 = x[q] - __bfloat162float(bh);
        __nv_bfloat16 bm = __float2bfloat16(r1);
        h[q] = __bfloat16_as_ushort(bh);
        m[q] = __bfloat16_as_ushort(bm);
    }
    vh = pack8(h); vm = pack8(m);
}

__device__ __forceinline__ void prep_store(uint4* base, int r, int c, int kg, uint4 v) {
    int tile = r >> 7, row = r & 127;
    base[((size_t)tile * CH_ST + c) * 1024 + row * 8 + (kg ^ (row & 7))] = v;
}

// ============================ prep A (text) ============================

__global__ void k_prep_A(const float* __restrict__ text) {
    int item = blockIdx.x * blockDim.x + threadIdx.x;   // BB*512*96
    if (item >= BB * 512 * 96) return;
    int ks = item % 96;
    int r  = (item / 96) & 511;
    int b  = item / (96 * 512);
    float x[8];
    if (r < SQ) {
        const float* src = text + ((size_t)b * SS + r + 1) * DD + ks * 8;
#pragma unroll
        for (int q = 0; q < 8; q++) x[q] = src[q];
    } else {
#pragma unroll
        for (int q = 0; q < 8; q++) x[q] = 0.f;
    }
    uint4 vh, vm;
    split8(x, vh, vm);
    uint4* base = g_Apre + (size_t)b * 4 * CH_ST * 1024;
    int c = ks >> 3, kg = ks & 7;
    prep_store(base, r, c, kg, vh);
    prep_store(base, r, 12 + c, kg, vm);
}

// ============================ fused target pass ============================
// One warp per (b, source-row sr): prep_B split/store + invnorm + imgloss.

__global__ __launch_bounds__(256) void k_fuse_tgt(const float* __restrict__ target,
                                                  const float* __restrict__ image) {
    int row = blockIdx.x * 8 + (threadIdx.x >> 5);   // 0 .. BB*512-1
    int lane = threadIdx.x & 31;
    int b = row >> 9, sr = row & 511;
    const float4* tg = reinterpret_cast<const float4*>(
        target + (size_t)(b * SS + sr) * DD);
    const float4* im = reinterpret_cast<const float4*>(
        image + (size_t)(b * SS + sr) * DD);

    float st = 0.f, sd = 0.f;
    uint4 vh[3], vm[3];
#pragma unroll
    for (int q = 0; q < 3; q++) {
        int g = lane + q * 32;                  // 8-elem group 0..95
        float4 t0 = tg[2 * g], t1 = tg[2 * g + 1];
        float4 i0 = im[2 * g], i1 = im[2 * g + 1];
        st += t0.x * t0.x + t0.y * t0.y + t0.z * t0.z + t0.w * t0.w
            + t1.x * t1.x + t1.y * t1.y + t1.z * t1.z + t1.w * t1.w;
        float d;
        d = t0.x - i0.x; sd += d * d;  d = t0.y - i0.y; sd += d * d;
        d = t0.z - i0.z; sd += d * d;  d = t0.w - i0.w; sd += d * d;
        d = t1.x - i1.x; sd += d * d;  d = t1.y - i1.y; sd += d * d;
        d = t1.z - i1.z; sd += d * d;  d = t1.w - i1.w; sd += d * d;
        float x[8] = {t0.x, t0.y, t0.z, t0.w, t1.x, t1.y, t1.z, t1.w};
        split8(x, vh[q], vm[q]);
    }
#pragma unroll
    for (int o = 16; o > 0; o >>= 1) {
        st += __shfl_xor_sync(0xffffffffu, st, o);
        sd += __shfl_xor_sync(0xffffffffu, sd, o);
    }

    __shared__ float bsum[8];
    if (lane == 0) bsum[threadIdx.x >> 5] = sd;
    __syncthreads();
    if (threadIdx.x == 0) {
        float t = 0.f;
#pragma unroll
        for (int w = 0; w < 8; w++) t += bsum[w];
        atomicAdd(&g_img_sum, t);
    }

    if (sr >= 1) {
        int r = sr - 1;                         // dest row 0..510
        if (lane == 0) g_invn[b * SQ + r] = rsqrtf(st);
        uint4* base = g_Bpre + (size_t)b * 4 * CH_ST * 1024;
#pragma unroll
        for (int q = 0; q < 3; q++) {
            int g = lane + q * 32;
            prep_store(base, r, g >> 3, g & 7, vh[q]);
            prep_store(base, r, 12 + (g >> 3), g & 7, vm[q]);
        }
    }
}

// ============================ GEMM + top-2 argmax (persistent) ============================
// 148 persistent CTAs; each loops over 128x128 tiles. Per tile: stage =
// {A_hi, A_mid, B_hi, B_mid} (64KB), 3 MMA passes per chunk (hh, hm, mh),
// 3-stage cp.async. Mainloop body identical to the known-good version.

#define STAGE_SZ 65536
#define SMEM_DYN (3 * STAGE_SZ + 512)

#define LDSM_X4(r0, r1, r2, r3, addr) \
    asm volatile("ldmatrix.sync.aligned.m8n8.x4.shared.b16 {%0,%1,%2,%3}, [%4];" \
                 : "=r"(r0), "=r"(r1), "=r"(r2), "=r"(r3) : "r"(addr))

#define MMA16816(c, a, b0, b1) \
    asm volatile("mma.sync.aligned.m16n8k16.row.col.f32.bf16.bf16.f32 " \
                 "{%0,%1,%2,%3}, {%4,%5,%6,%7}, {%8,%9}, {%0,%1,%2,%3};" \
                 : "+f"((c)[0]), "+f"((c)[1]), "+f"((c)[2]), "+f"((c)[3]) \
                 : "r"((a)[0]), "r"((a)[1]), "r"((a)[2]), "r"((a)[3]), \
                   "r"(b0), "r"(b1))

__global__ __launch_bounds__(256, 1) void k_gemm() {
    extern __shared__ __align__(16) char sm[];
    uint32_t smb = smem_u32(sm);
    int tid = threadIdx.x, lane = tid & 31, wid = tid >> 5;
    int warpM = (wid & 1) * 64, warpN = (wid >> 1) * 32;

    float* Inv = (float*)(sm + 3 * STAGE_SZ);

    // tile-independent lane mappings
    int lrow = lane & 15, khalf = lane >> 4;
    int aRowTerm[4], aRowMask[4];
#pragma unroll
    for (int mt = 0; mt < 4; mt++) {
        int row = warpM + mt * 16 + lrow;
        aRowTerm[mt] = row * 128;
        aRowMask[mt] = row & 7;
    }
    int bg8 = lane >> 3, bl8 = lane & 7;
    int bRow0 = warpN + ((bg8 >> 1) << 3) + bl8;
    int bKg = bg8 & 1;
    int bRowTerm[2], bRowMask[2];
#pragma unroll
    for (int nb = 0; nb < 2; nb++) {
        int row = bRow0 + nb * 16;
        bRowTerm[nb] = row * 128;
        bRowMask[nb] = row & 7;
    }
    int gid = lane >> 2, tig = lane & 3;

    for (int t = blockIdx.x; t < NTILES; t += gridDim.x) {
        int b = t >> 4;
        int rest = t & 15;
        int itile = rest >> 2, jtile = rest & 3;

        if (tid < 128) {
            int j = jtile * 128 + tid;
            Inv[tid] = (j < SQ) ? g_invn[b * SQ + j] : 0.f;
        }

        const char* Asrc = (const char*)(g_Apre + (size_t)(b * 4 + itile) * CH_ST * 1024);
        const char* Bsrc = (const char*)(g_Bpre + (size_t)(b * 4 + jtile) * CH_ST * 1024);

        float acc[4][4][4];
#pragma unroll
        for (int mt = 0; mt < 4; mt++)
#pragma unroll
            for (int n8 = 0; n8 < 4; n8++)
#pragma unroll
                for (int e = 0; e < 4; e++) acc[mt][n8][e] = 0.f;

#define STAGE_COPY(c, s) do {                                                   \
    uint32_t d = smb + (s) * STAGE_SZ + tid * 16;                               \
    const char* gAh = Asrc + (size_t)(c) * 16384 + tid * 16;                    \
    const char* gAm = Asrc + (size_t)((c) + 12) * 16384 + tid * 16;             \
    const char* gBh = Bsrc + (size_t)(c) * 16384 + tid * 16;                    \
    const char* gBm = Bsrc + (size_t)((c) + 12) * 16384 + tid * 16;             \
    _Pragma("unroll")                                                           \
    for (int it = 0; it < 4; it++) {                                            \
        asm volatile("cp.async.cg.shared.global [%0], [%1], 16;"                \
                     :: "r"(d + it * 4096), "l"(gAh + it * 4096));              \
        asm volatile("cp.async.cg.shared.global [%0], [%1], 16;"                \
                     :: "r"(d + 16384 + it * 4096), "l"(gAm + it * 4096));      \
        asm volatile("cp.async.cg.shared.global [%0], [%1], 16;"                \
                     :: "r"(d + 32768 + it * 4096), "l"(gBh + it * 4096));      \
        asm volatile("cp.async.cg.shared.global [%0], [%1], 16;"                \
                     :: "r"(d + 49152 + it * 4096), "l"(gBm + it * 4096));      \
    }                                                                           \
    asm volatile("cp.async.commit_group;");                                     \
} while (0)

        STAGE_COPY(0, 0);
        STAGE_COPY(1, 1);

        for (int c = 0; c < KCH; c++) {
            if (c + 1 < KCH) asm volatile("cp.async.wait_group 1;");
            else             asm volatile("cp.async.wait_group 0;");
            __syncthreads();
            if (c + 2 < KCH) STAGE_COPY(c + 2, (c + 2) % 3);

            uint32_t stg = smb + (c % 3) * STAGE_SZ;
            uint32_t aHi = stg, aMi = stg + 16384, bHi = stg + 32768, bMi = stg + 49152;

#pragma unroll
            for (int ks = 0; ks < 4; ks++) {
                int kgA = ks * 2 + khalf;
                int kgB = ks * 2 + bKg;
                uint32_t ah[4][4], am[4][4], bh[2][4], bm[2][4];
#pragma unroll
                for (int nb = 0; nb < 2; nb++) {
                    uint32_t off = bRowTerm[nb] + ((kgB ^ bRowMask[nb]) << 4);
                    LDSM_X4(bh[nb][0], bh[nb][1], bh[nb][2], bh[nb][3], bHi + off);
                    LDSM_X4(bm[nb][0], bm[nb][1], bm[nb][2], bm[nb][3], bMi + off);
                }
#pragma unroll
                for (int mt = 0; mt < 4; mt++) {
                    uint32_t off = aRowTerm[mt] + ((kgA ^ aRowMask[mt]) << 4);
                    LDSM_X4(ah[mt][0], ah[mt][1], ah[mt][2], ah[mt][3], aHi + off);
                }
                // pass 1: hi * hi
#pragma unroll
                for (int mt = 0; mt < 4; mt++)
#pragma unroll
                    for (int n8 = 0; n8 < 4; n8++)
                        MMA16816(acc[mt][n8], ah[mt],
                                 bh[n8 >> 1][(n8 & 1) * 2],
                                 bh[n8 >> 1][(n8 & 1) * 2 + 1]);
#pragma unroll
                for (int mt = 0; mt < 4; mt++) {
                    uint32_t off = aRowTerm[mt] + ((kgA ^ aRowMask[mt]) << 4);
                    LDSM_X4(am[mt][0], am[mt][1], am[mt][2], am[mt][3], aMi + off);
                }
                // pass 2: hi * mid
#pragma unroll
                for (int mt = 0; mt < 4; mt++)
#pragma unroll
                    for (int n8 = 0; n8 < 4; n8++)
                        MMA16816(acc[mt][n8], ah[mt],
                                 bm[n8 >> 1][(n8 & 1) * 2],
                                 bm[n8 >> 1][(n8 & 1) * 2 + 1]);
                // pass 3: mid * hi
#pragma unroll
                for (int mt = 0; mt < 4; mt++)
#pragma unroll
                    for (int n8 = 0; n8 < 4; n8++)
                        MMA16816(acc[mt][n8], am[mt],
                                 bh[n8 >> 1][(n8 & 1) * 2],
                                 bh[n8 >> 1][(n8 & 1) * 2 + 1]);
            }
        }
#undef STAGE_COPY

        // epilogue: per-row top-2 within this 128-j tile, no atomics.
        float* sv1 = (float*)sm;             // [128][4]
        int*   sj1 = (int*)(sm + 2048);      // [128][4]
        float* sv2 = (float*)(sm + 4096);    // [128][4]

#pragma unroll
        for (int mt = 0; mt < 4; mt++) {
#pragma unroll
            for (int rh = 0; rh < 2; rh++) {
                int iloc = warpM + mt * 16 + gid + rh * 8;
                float v1 = NEG_INF, v2 = NEG_INF;
                int j1 = 1 << 30;
#pragma unroll
                for (int n8 = 0; n8 < 4; n8++) {
#pragma unroll
                    for (int e = 0; e < 2; e++) {
                        int jloc = warpN + n8 * 8 + tig * 2 + e;
                        int j = jtile * 128 + jloc;
                        float v = (j < SQ) ? acc[mt][n8][rh * 2 + e] * Inv[jloc]
                                           : NEG_INF;
                        if (v > v1) { v2 = v1; v1 = v; j1 = j; }
                        else if (v > v2) v2 = v;
                    }
                }
#pragma unroll
                for (int o = 1; o <= 2; o <<= 1) {
                    float ov1 = __shfl_xor_sync(0xffffffffu, v1, o);
                    float ov2 = __shfl_xor_sync(0xffffffffu, v2, o);
                    int   oj  = __shfl_xor_sync(0xffffffffu, j1, o);
                    if (ov1 > v1 || (ov1 == v1 && oj < j1)) {
                        v2 = fmaxf(v1, ov2); v1 = ov1; j1 = oj;
                    } else {
                        v2 = fmaxf(v2, ov1);
                    }
                }
                if (tig == 0) {
                    int s = iloc * 4 + (wid >> 1);
                    sv1[s] = v1; sj1[s] = j1; sv2[s] = v2;
                }
            }
        }
        __syncthreads();

        if (tid < 128) {
            float v1 = NEG_INF, v2 = NEG_INF;
            int j1 = 1 << 30;
#pragma unroll
            for (int q = 0; q < 4; q++) {
                float a1 = sv1[tid * 4 + q];
                float a2 = sv2[tid * 4 + q];
                int   aj = sj1[tid * 4 + q];
                if (a1 > v1 || (a1 == v1 && aj < j1)) {
                    v2 = fmaxf(v1, a2); v1 = a1; j1 = aj;
                } else {
                    v2 = fmaxf(v2, a1);
                }
            }
            int i = itile * 128 + tid;
            if (i < SQ) {
                int s = (b * SQ + i) * 4 + jtile;
                g_pv1[s] = v1; g_pj1[s] = j1; g_pv2[s] = v2;
            }
        }
        __syncthreads();   // protect epilogue scratch (stage-0 smem) + Inv before next tile
    }
}

// merge 4 jtile partials per row; enqueue ambiguous rows.
__global__ void k_merge() {
    int n = blockIdx.x * blockDim.x + threadIdx.x;
    if (n >= NROWS) return;
    float v1 = NEG_INF, v2 = NEG_INF;
    int j1 = 1 << 30;
#pragma unroll
    for (int q = 0; q < 4; q++) {
        float a1 = g_pv1[n * 4 + q];
        float a2 = g_pv2[n * 4 + q];
        int   aj = g_pj1[n * 4 + q];
        if (a1 > v1 || (a1 == v1 && aj < j1)) {
            v2 = fmaxf(v1, a2); v1 = a1; j1 = aj;
        } else {
            v2 = fmaxf(v2, a1);
        }
    }
    g_idx[n] = j1;
    if (v1 - v2 < TAU) {
        int slot = atomicAdd(&g_qcnt, 1);
        g_queue[slot] = n;
    }
}

// exact fp32 rescore for ambiguous rows: one CTA (256 thr) per queue entry.
__global__ __launch_bounds__(256) void k_rescore(const float* __restrict__ text,
                                                 const float* __restrict__ target) {
    __shared__ float4 txs[DD / 4];
    __shared__ float wv[8];
    __shared__ int   wj[8];
    int cnt = g_qcnt;
    for (int q = blockIdx.x; q < cnt; q += gridDim.x) {
        int row = g_queue[q];
        int b = row / SQ, i = row % SQ;
        __syncthreads();
        {
            const float4* src = reinterpret_cast<const float4*>(
                text + ((size_t)b * SS + i + 1) * DD);
            for (int d = threadIdx.x; d < DD / 4; d += 256) txs[d] = src[d];
        }
        __syncthreads();
        int wd = threadIdx.x >> 5, lane = threadIdx.x & 31;
        float best = NEG_INF;
        int bj = 0;
        for (int j = wd; j < SQ; j += 8) {
            const float4* tg = reinterpret_cast<const float4*>(
                target + ((size_t)b * SS + j + 1) * DD);
            float s = 0.f;
#pragma unroll
            for (int it = 0; it < DD / 128; it++) {
                float4 a = txs[lane + it * 32];
                float4 c = tg[lane + it * 32];
                s += a.x * c.x + a.y * c.y + a.z * c.z + a.w * c.w;
            }
#pragma unroll
            for (int o = 16; o > 0; o >>= 1) s += __shfl_xor_sync(0xffffffffu, s, o);
            float v = s * g_invn[b * SQ + j];
            if (v > best) { best = v; bj = j; }
        }
        if (lane == 0) { wv[wd] = best; wj[wd] = bj; }
        __syncthreads();
        if (threadIdx.x == 0) {
            float B = wv[0]; int J = wj[0];
#pragma unroll
            for (int w = 1; w < 8; w++)
                if (wv[w] > B || (wv[w] == B && wj[w] < J)) { B = wv[w]; J = wj[w]; }
            g_idx[row] = J;
        }
    }
}

// ============================ text loss ============================

__global__ __launch_bounds__(256) void k_txtloss(const float* __restrict__ text,
                                                 const float* __restrict__ target,
                                                 const int* __restrict__ pm) {
    int row = blockIdx.x * 8 + (threadIdx.x >> 5);
    if (row >= NROWS) return;
    int lane = threadIdx.x & 31;
    int b = row / SQ, i = row % SQ;
    if (pm[b * SS + i + 1] != 0) return;
    int id = g_idx[row];
    const float4* pt = reinterpret_cast<const float4*>(
        text + (size_t)b * SS * DD + (size_t)(i + 1) * DD);
    const float4* pa = reinterpret_cast<const float4*>(
        target + (size_t)b * SS * DD + (size_t)(id + 1) * DD);
    float s = 0.f;
#pragma unroll
    for (int it = 0; it < DD / 128; it++) {
        float4 a = pt[lane + it * 32];
        float4 c = pa[lane + it * 32];
        float dx = a.x - c.x, dy = a.y - c.y, dz = a.z - c.z, dw = a.w - c.w;
        s += dx * dx + dy * dy + dz * dz + dw * dw;
    }
#pragma unroll
    for (int o = 16; o > 0; o >>= 1) s += __shfl_xor_sync(0xffffffffu, s, o);
    if (lane == 0) {
        atomicAdd(&g_txt_sum, s);
        atomicAdd(&g_valid, 1);
    }
}

// final: scalars + idx -> out (fused finalize + idxcopy)
__global__ void k_final(float* __restrict__ out) {
    int n = blockIdx.x * blockDim.x + threadIdx.x;
    if (n == 0) {
        float kt = g_txt_sum / ((float)g_valid * (float)DD);
        float ki = g_img_sum / (float)(BB * SS * DD);
        out[0] = 0.5f * (kt + ki);
        out[1] = kt;
        out[2] = ki;
    }
    if (n < NROWS) out[3 + n] = (float)g_idx[n];
}

// ============================ launch ============================

extern "C" void kernel_launch(void* const* d_in, const int* in_sizes, int n_in,
                              void* d_out, int out_size) {
    const float* image  = (const float*)d_in[0];
    const float* text   = (const float*)d_in[1];
    const float* target = (const float*)d_in[2];
    const int*   pm     = (const int*)d_in[3];
    float* out = (float*)d_out;

    static cudaStream_t s1 = nullptr;
    static cudaEvent_t ev0 = nullptr, ev1 = nullptr;
    if (s1 == nullptr) {
        cudaStreamCreateWithFlags(&s1, cudaStreamNonBlocking);
        cudaEventCreateWithFlags(&ev0, cudaEventDisableTiming);
        cudaEventCreateWithFlags(&ev1, cudaEventDisableTiming);
        cudaFuncSetAttribute(k_gemm, cudaFuncAttributeMaxDynamicSharedMemorySize,
                             SMEM_DYN);
    }

    k_init<<<1, 1>>>();

    // fork: fuse_tgt (target+image pass) overlaps prep_A (text pass)
    cudaEventRecord(ev0, 0);
    cudaStreamWaitEvent(s1, ev0, 0);
    k_fuse_tgt<<<BB * 512 / 8, 256, 0, s1>>>(target, image);
    cudaEventRecord(ev1, s1);

    k_prep_A<<<(BB * 512 * 96 + 255) / 256, 256>>>(text);

    // join: GEMM needs both prep outputs
    cudaStreamWaitEvent(0, ev1, 0);
    k_gemm<<<148, 256, SMEM_DYN>>>();

    k_merge<<<(NROWS + 255) / 256, 256>>>();
    k_rescore<<<512, 256>>>(text, target);
    k_txtloss<<<(NROWS + 7) / 8, 256>>>(text, target, pm);
    k_final<<<(NROWS + 255) / 256, 256>>>(out);
}

// round 17
// speedup vs baseline: 1.0186x; 1.0186x over previous
#include <cuda_runtime.h>
#include <cuda_bf16.h>
#include <cstdint>

#define BB 32
#define SS 512
#define DD 768
#define SQ 511
#define NROWS (BB*SQ)
#define NEG_INF __int_as_float(0xff800000)

#define KCH 12             // 12 k-chunks of 64 over D=768
#define CH_ST 24           // stored chunks per (b,tile): hi[0..11], mid[12..23]
#define TAU 1e-4f
#define GB 8               // batches per pipeline group
#define NGRP (BB/GB)       // 4 groups

// prepped tiles: [b][tile(0..3)][chunk(0..23)][128 rows x 64 bf16, swizzled]
__device__ uint4 g_Apre[(size_t)BB * 4 * CH_ST * 1024];
__device__ uint4 g_Bpre[(size_t)BB * 4 * CH_ST * 1024];
__device__ float g_invn[NROWS];
__device__ float g_pv1[NROWS * 4];
__device__ int   g_pj1[NROWS * 4];
__device__ float g_pv2[NROWS * 4];
__device__ int   g_idx[NROWS];
__device__ int   g_queue[NROWS];
__device__ int   g_qcnt;
__device__ float g_txt_sum;
__device__ float g_img_sum;
__device__ int   g_valid;

__device__ __forceinline__ uint32_t smem_u32(const void* p) {
    uint32_t a;
    asm("{ .reg .u64 t; cvta.to.shared.u64 t, %1; cvt.u32.u64 %0, t; }"
        : "=r"(a) : "l"(p));
    return a;
}

// ============================ init ============================

__global__ void k_init() {
    g_txt_sum = 0.f; g_img_sum = 0.f; g_valid = 0; g_qcnt = 0;
}

// ============================ prep helpers ============================

__device__ __forceinline__ uint4 pack8(const unsigned short* u) {
    uint4 v;
    v.x = (uint32_t)u[0] | ((uint32_t)u[1] << 16);
    v.y = (uint32_t)u[2] | ((uint32_t)u[3] << 16);
    v.z = (uint32_t)u[4] | ((uint32_t)u[5] << 16);
    v.w = (uint32_t)u[6] | ((uint32_t)u[7] << 16);
    return v;
}

__device__ __forceinline__ void split8(const float* x, uint4& vh, uint4& vm) {
    unsigned short h[8], m[8];
#pragma unroll
    for (int q = 0; q < 8; q++) {
        __nv_bfloat16 bh = __float2bfloat16(x[q]);
        float r1 = x[q] - __bfloat162float(bh);
        __nv_bfloat16 bm = __float2bfloat16(r1);
        h[q] = __bfloat16_as_ushort(bh);
        m[q] = __bfloat16_as_ushort(bm);
    }
    vh = pack8(h); vm = pack8(m);
}

__device__ __forceinline__ void prep_store(uint4* base, int r, int c, int kg, uint4 v) {
    int tile = r >> 7, row = r & 127;
    base[((size_t)tile * CH_ST + c) * 1024 + row * 8 + (kg ^ (row & 7))] = v;
}

// ============================ prep A (text), one batch group ============================

__global__ void k_prep_A(const float* __restrict__ text, int b0) {
    int item = blockIdx.x * blockDim.x + threadIdx.x;   // GB*512*96
    if (item >= GB * 512 * 96) return;
    int ks = item % 96;
    int r  = (item / 96) & 511;
    int b  = b0 + item / (96 * 512);
    float x[8];
    if (r < SQ) {
        const float* src = text + ((size_t)b * SS + r + 1) * DD + ks * 8;
#pragma unroll
        for (int q = 0; q < 8; q++) x[q] = src[q];
    } else {
#pragma unroll
        for (int q = 0; q < 8; q++) x[q] = 0.f;
    }
    uint4 vh, vm;
    split8(x, vh, vm);
    uint4* base = g_Apre + (size_t)b * 4 * CH_ST * 1024;
    int c = ks >> 3, kg = ks & 7;
    prep_store(base, r, c, kg, vh);
    prep_store(base, r, 12 + c, kg, vm);
}

// ============================ fused target pass, one batch group ============================
// One warp per (b, source-row sr): prep_B split/store + invnorm + imgloss.

__global__ __launch_bounds__(256) void k_fuse_tgt(const float* __restrict__ target,
                                                  const float* __restrict__ image,
                                                  int b0) {
    int row = b0 * 512 + blockIdx.x * 8 + (threadIdx.x >> 5);
    int lane = threadIdx.x & 31;
    int b = row >> 9, sr = row & 511;
    const float4* tg = reinterpret_cast<const float4*>(
        target + (size_t)(b * SS + sr) * DD);
    const float4* im = reinterpret_cast<const float4*>(
        image + (size_t)(b * SS + sr) * DD);

    float st = 0.f, sd = 0.f;
    uint4 vh[3], vm[3];
#pragma unroll
    for (int q = 0; q < 3; q++) {
        int g = lane + q * 32;                  // 8-elem group 0..95
        float4 t0 = tg[2 * g], t1 = tg[2 * g + 1];
        float4 i0 = im[2 * g], i1 = im[2 * g + 1];
        st += t0.x * t0.x + t0.y * t0.y + t0.z * t0.z + t0.w * t0.w
            + t1.x * t1.x + t1.y * t1.y + t1.z * t1.z + t1.w * t1.w;
        float d;
        d = t0.x - i0.x; sd += d * d;  d = t0.y - i0.y; sd += d * d;
        d = t0.z - i0.z; sd += d * d;  d = t0.w - i0.w; sd += d * d;
        d = t1.x - i1.x; sd += d * d;  d = t1.y - i1.y; sd += d * d;
        d = t1.z - i1.z; sd += d * d;  d = t1.w - i1.w; sd += d * d;
        float x[8] = {t0.x, t0.y, t0.z, t0.w, t1.x, t1.y, t1.z, t1.w};
        split8(x, vh[q], vm[q]);
    }
#pragma unroll
    for (int o = 16; o > 0; o >>= 1) {
        st += __shfl_xor_sync(0xffffffffu, st, o);
        sd += __shfl_xor_sync(0xffffffffu, sd, o);
    }

    __shared__ float bsum[8];
    if (lane == 0) bsum[threadIdx.x >> 5] = sd;
    __syncthreads();
    if (threadIdx.x == 0) {
        float t = 0.f;
#pragma unroll
        for (int w = 0; w < 8; w++) t += bsum[w];
        atomicAdd(&g_img_sum, t);
    }

    if (sr >= 1) {
        int r = sr - 1;                         // dest row 0..510
        if (lane == 0) g_invn[b * SQ + r] = rsqrtf(st);
        uint4* base = g_Bpre + (size_t)b * 4 * CH_ST * 1024;
#pragma unroll
        for (int q = 0; q < 3; q++) {
            int g = lane + q * 32;
            prep_store(base, r, g >> 3, g & 7, vh[q]);
            prep_store(base, r, 12 + (g >> 3), g & 7, vm[q]);
        }
    }
}

// ============================ GEMM + top-2 argmax (per group) ============================
// grid = (16, GB); b = b0 + blockIdx.y. Stage = {A_hi, A_mid, B_hi, B_mid}
// (64KB); 3 MMA passes per chunk (hh, hm, mh). 3-stage cp.async. Known-good
// mainloop — do not touch.

#define STAGE_SZ 65536
#define SMEM_DYN (3 * STAGE_SZ + 512)

#define LDSM_X4(r0, r1, r2, r3, addr) \
    asm volatile("ldmatrix.sync.aligned.m8n8.x4.shared.b16 {%0,%1,%2,%3}, [%4];" \
                 : "=r"(r0), "=r"(r1), "=r"(r2), "=r"(r3) : "r"(addr))

#define MMA16816(c, a, b0, b1) \
    asm volatile("mma.sync.aligned.m16n8k16.row.col.f32.bf16.bf16.f32 " \
                 "{%0,%1,%2,%3}, {%4,%5,%6,%7}, {%8,%9}, {%0,%1,%2,%3};" \
                 : "+f"((c)[0]), "+f"((c)[1]), "+f"((c)[2]), "+f"((c)[3]) \
                 : "r"((a)[0]), "r"((a)[1]), "r"((a)[2]), "r"((a)[3]), \
                   "r"(b0), "r"(b1))

__global__ __launch_bounds__(256, 1) void k_gemm(int b0) {
    extern __shared__ __align__(16) char sm[];
    uint32_t smb = smem_u32(sm);
    int tid = threadIdx.x, lane = tid & 31, wid = tid >> 5;
    int bx = blockIdx.x;
    int itile = bx >> 2, jtile = bx & 3;
    int b = b0 + blockIdx.y;
    int warpM = (wid & 1) * 64, warpN = (wid >> 1) * 32;

    float* Inv = (float*)(sm + 3 * STAGE_SZ);
    if (tid < 128) {
        int j = jtile * 128 + tid;
        Inv[tid] = (j < SQ) ? g_invn[b * SQ + j] : 0.f;
    }

    const char* Asrc = (const char*)(g_Apre + (size_t)(b * 4 + itile) * CH_ST * 1024);
    const char* Bsrc = (const char*)(g_Bpre + (size_t)(b * 4 + jtile) * CH_ST * 1024);

    float acc[4][4][4];
#pragma unroll
    for (int mt = 0; mt < 4; mt++)
#pragma unroll
        for (int n8 = 0; n8 < 4; n8++)
#pragma unroll
            for (int e = 0; e < 4; e++) acc[mt][n8][e] = 0.f;

#define STAGE_COPY(c, s) do {                                                   \
    uint32_t d = smb + (s) * STAGE_SZ + tid * 16;                               \
    const char* gAh = Asrc + (size_t)(c) * 16384 + tid * 16;                    \
    const char* gAm = Asrc + (size_t)((c) + 12) * 16384 + tid * 16;             \
    const char* gBh = Bsrc + (size_t)(c) * 16384 + tid * 16;                    \
    const char* gBm = Bsrc + (size_t)((c) + 12) * 16384 + tid * 16;             \
    _Pragma("unroll")                                                           \
    for (int it = 0; it < 4; it++) {                                            \
        asm volatile("cp.async.cg.shared.global [%0], [%1], 16;"                \
                     :: "r"(d + it * 4096), "l"(gAh + it * 4096));              \
        asm volatile("cp.async.cg.shared.global [%0], [%1], 16;"                \
                     :: "r"(d + 16384 + it * 4096), "l"(gAm + it * 4096));      \
        asm volatile("cp.async.cg.shared.global [%0], [%1], 16;"                \
                     :: "r"(d + 32768 + it * 4096), "l"(gBh + it * 4096));      \
        asm volatile("cp.async.cg.shared.global [%0], [%1], 16;"                \
                     :: "r"(d + 49152 + it * 4096), "l"(gBm + it * 4096));      \
    }                                                                           \
    asm volatile("cp.async.commit_group;");                                     \
} while (0)

    STAGE_COPY(0, 0);
    STAGE_COPY(1, 1);

    int lrow = lane & 15, khalf = lane >> 4;
    int aRowTerm[4], aRowMask[4];
#pragma unroll
    for (int mt = 0; mt < 4; mt++) {
        int row = warpM + mt * 16 + lrow;
        aRowTerm[mt] = row * 128;
        aRowMask[mt] = row & 7;
    }
    int bg8 = lane >> 3, bl8 = lane & 7;
    int bRow0 = warpN + ((bg8 >> 1) << 3) + bl8;
    int bKg = bg8 & 1;
    int bRowTerm[2], bRowMask[2];
#pragma unroll
    for (int nb = 0; nb < 2; nb++) {
        int row = bRow0 + nb * 16;
        bRowTerm[nb] = row * 128;
        bRowMask[nb] = row & 7;
    }

    for (int c = 0; c < KCH; c++) {
        if (c + 1 < KCH) asm volatile("cp.async.wait_group 1;");
        else             asm volatile("cp.async.wait_group 0;");
        __syncthreads();
        if (c + 2 < KCH) STAGE_COPY(c + 2, (c + 2) % 3);

        uint32_t stg = smb + (c % 3) * STAGE_SZ;
        uint32_t aHi = stg, aMi = stg + 16384, bHi = stg + 32768, bMi = stg + 49152;

#pragma unroll
        for (int ks = 0; ks < 4; ks++) {
            int kgA = ks * 2 + khalf;
            int kgB = ks * 2 + bKg;
            uint32_t ah[4][4], am[4][4], bh[2][4], bm[2][4];
#pragma unroll
            for (int nb = 0; nb < 2; nb++) {
                uint32_t off = bRowTerm[nb] + ((kgB ^ bRowMask[nb]) << 4);
                LDSM_X4(bh[nb][0], bh[nb][1], bh[nb][2], bh[nb][3], bHi + off);
                LDSM_X4(bm[nb][0], bm[nb][1], bm[nb][2], bm[nb][3], bMi + off);
            }
#pragma unroll
            for (int mt = 0; mt < 4; mt++) {
                uint32_t off = aRowTerm[mt] + ((kgA ^ aRowMask[mt]) << 4);
                LDSM_X4(ah[mt][0], ah[mt][1], ah[mt][2], ah[mt][3], aHi + off);
            }
            // pass 1: hi * hi
#pragma unroll
            for (int mt = 0; mt < 4; mt++)
#pragma unroll
                for (int n8 = 0; n8 < 4; n8++)
                    MMA16816(acc[mt][n8], ah[mt],
                             bh[n8 >> 1][(n8 & 1) * 2],
                             bh[n8 >> 1][(n8 & 1) * 2 + 1]);
#pragma unroll
            for (int mt = 0; mt < 4; mt++) {
                uint32_t off = aRowTerm[mt] + ((kgA ^ aRowMask[mt]) << 4);
                LDSM_X4(am[mt][0], am[mt][1], am[mt][2], am[mt][3], aMi + off);
            }
            // pass 2: hi * mid
#pragma unroll
            for (int mt = 0; mt < 4; mt++)
#pragma unroll
                for (int n8 = 0; n8 < 4; n8++)
                    MMA16816(acc[mt][n8], ah[mt],
                             bm[n8 >> 1][(n8 & 1) * 2],
                             bm[n8 >> 1][(n8 & 1) * 2 + 1]);
            // pass 3: mid * hi
#pragma unroll
            for (int mt = 0; mt < 4; mt++)
#pragma unroll
                for (int n8 = 0; n8 < 4; n8++)
                    MMA16816(acc[mt][n8], am[mt],
                             bh[n8 >> 1][(n8 & 1) * 2],
                             bh[n8 >> 1][(n8 & 1) * 2 + 1]);
        }
    }
#undef STAGE_COPY

    // epilogue: per-row top-2 within this 128-j tile, no atomics.
    float* sv1 = (float*)sm;             // [128][4]
    int*   sj1 = (int*)(sm + 2048);      // [128][4]
    float* sv2 = (float*)(sm + 4096);    // [128][4]

    int gid = lane >> 2, tig = lane & 3;
#pragma unroll
    for (int mt = 0; mt < 4; mt++) {
#pragma unroll
        for (int rh = 0; rh < 2; rh++) {
            int iloc = warpM + mt * 16 + gid + rh * 8;
            float v1 = NEG_INF, v2 = NEG_INF;
            int j1 = 1 << 30;
#pragma unroll
            for (int n8 = 0; n8 < 4; n8++) {
#pragma unroll
                for (int e = 0; e < 2; e++) {
                    int jloc = warpN + n8 * 8 + tig * 2 + e;
                    int j = jtile * 128 + jloc;
                    float v = (j < SQ) ? acc[mt][n8][rh * 2 + e] * Inv[jloc]
                                       : NEG_INF;
                    if (v > v1) { v2 = v1; v1 = v; j1 = j; }
                    else if (v > v2) v2 = v;
                }
            }
#pragma unroll
            for (int o = 1; o <= 2; o <<= 1) {
                float ov1 = __shfl_xor_sync(0xffffffffu, v1, o);
                float ov2 = __shfl_xor_sync(0xffffffffu, v2, o);
                int   oj  = __shfl_xor_sync(0xffffffffu, j1, o);
                if (ov1 > v1 || (ov1 == v1 && oj < j1)) {
                    v2 = fmaxf(v1, ov2); v1 = ov1; j1 = oj;
                } else {
                    v2 = fmaxf(v2, ov1);
                }
            }
            if (tig == 0) {
                int s = iloc * 4 + (wid >> 1);
                sv1[s] = v1; sj1[s] = j1; sv2[s] = v2;
            }
        }
    }
    __syncthreads();

    if (tid < 128) {
        float v1 = NEG_INF, v2 = NEG_INF;
        int j1 = 1 << 30;
#pragma unroll
        for (int q = 0; q < 4; q++) {
            float a1 = sv1[tid * 4 + q];
            float a2 = sv2[tid * 4 + q];
            int   aj = sj1[tid * 4 + q];
            if (a1 > v1 || (a1 == v1 && aj < j1)) {
                v2 = fmaxf(v1, a2); v1 = a1; j1 = aj;
            } else {
                v2 = fmaxf(v2, a1);
            }
        }
        int i = itile * 128 + tid;
        if (i < SQ) {
            int s = (b * SQ + i) * 4 + jtile;
            g_pv1[s] = v1; g_pj1[s] = j1; g_pv2[s] = v2;
        }
    }
}

// merge 4 jtile partials per row; enqueue ambiguous rows.
__global__ void k_merge() {
    int n = blockIdx.x * blockDim.x + threadIdx.x;
    if (n >= NROWS) return;
    float v1 = NEG_INF, v2 = NEG_INF;
    int j1 = 1 << 30;
#pragma unroll
    for (int q = 0; q < 4; q++) {
        float a1 = g_pv1[n * 4 + q];
        float a2 = g_pv2[n * 4 + q];
        int   aj = g_pj1[n * 4 + q];
        if (a1 > v1 || (a1 == v1 && aj < j1)) {
            v2 = fmaxf(v1, a2); v1 = a1; j1 = aj;
        } else {
            v2 = fmaxf(v2, a1);
        }
    }
    g_idx[n] = j1;
    if (v1 - v2 < TAU) {
        int slot = atomicAdd(&g_qcnt, 1);
        g_queue[slot] = n;
    }
}

// exact fp32 rescore for ambiguous rows: one CTA (256 thr) per queue entry.
__global__ __launch_bounds__(256) void k_rescore(const float* __restrict__ text,
                                                 const float* __restrict__ target) {
    __shared__ float4 txs[DD / 4];
    __shared__ float wv[8];
    __shared__ int   wj[8];
    int cnt = g_qcnt;
    for (int q = blockIdx.x; q < cnt; q += gridDim.x) {
        int row = g_queue[q];
        int b = row / SQ, i = row % SQ;
        __syncthreads();
        {
            const float4* src = reinterpret_cast<const float4*>(
                text + ((size_t)b * SS + i + 1) * DD);
            for (int d = threadIdx.x; d < DD / 4; d += 256) txs[d] = src[d];
        }
        __syncthreads();
        int wd = threadIdx.x >> 5, lane = threadIdx.x & 31;
        float best = NEG_INF;
        int bj = 0;
        for (int j = wd; j < SQ; j += 8) {
            const float4* tg = reinterpret_cast<const float4*>(
                target + ((size_t)b * SS + j + 1) * DD);
            float s = 0.f;
#pragma unroll
            for (int it = 0; it < DD / 128; it++) {
                float4 a = txs[lane + it * 32];
                float4 c = tg[lane + it * 32];
                s += a.x * c.x + a.y * c.y + a.z * c.z + a.w * c.w;
            }
#pragma unroll
            for (int o = 16; o > 0; o >>= 1) s += __shfl_xor_sync(0xffffffffu, s, o);
            float v = s * g_invn[b * SQ + j];
            if (v > best) { best = v; bj = j; }
        }
        if (lane == 0) { wv[wd] = best; wj[wd] = bj; }
        __syncthreads();
        if (threadIdx.x == 0) {
            float B = wv[0]; int J = wj[0];
#pragma unroll
            for (int w = 1; w < 8; w++)
                if (wv[w] > B || (wv[w] == B && wj[w] < J)) { B = wv[w]; J = wj[w]; }
            g_idx[row] = J;
        }
    }
}

// ============================ text loss ============================

__global__ __launch_bounds__(256) void k_txtloss(const float* __restrict__ text,
                                                 const float* __restrict__ target,
                                                 const int* __restrict__ pm) {
    int row = blockIdx.x * 8 + (threadIdx.x >> 5);
    if (row >= NROWS) return;
    int lane = threadIdx.x & 31;
    int b = row / SQ, i = row % SQ;
    if (pm[b * SS + i + 1] != 0) return;
    int id = g_idx[row];
    const float4* pt = reinterpret_cast<const float4*>(
        text + (size_t)b * SS * DD + (size_t)(i + 1) * DD);
    const float4* pa = reinterpret_cast<const float4*>(
        target + (size_t)b * SS * DD + (size_t)(id + 1) * DD);
    float s = 0.f;
#pragma unroll
    for (int it = 0; it < DD / 128; it++) {
        float4 a = pt[lane + it * 32];
        float4 c = pa[lane + it * 32];
        float dx = a.x - c.x, dy = a.y - c.y, dz = a.z - c.z, dw = a.w - c.w;
        s += dx * dx + dy * dy + dz * dz + dw * dw;
    }
#pragma unroll
    for (int o = 16; o > 0; o >>= 1) s += __shfl_xor_sync(0xffffffffu, s, o);
    if (lane == 0) {
        atomicAdd(&g_txt_sum, s);
        atomicAdd(&g_valid, 1);
    }
}

// final: scalars + idx -> out (fused finalize + idxcopy)
__global__ void k_final(float* __restrict__ out) {
    int n = blockIdx.x * blockDim.x + threadIdx.x;
    if (n == 0) {
        float kt = g_txt_sum / ((float)g_valid * (float)DD);
        float ki = g_img_sum / (float)(BB * SS * DD);
        out[0] = 0.5f * (kt + ki);
        out[1] = kt;
        out[2] = ki;
    }
    if (n < NROWS) out[3 + n] = (float)g_idx[n];
}

// ============================ launch ============================

extern "C" void kernel_launch(void* const* d_in, const int* in_sizes, int n_in,
                              void* d_out, int out_size) {
    const float* image  = (const float*)d_in[0];
    const float* text   = (const float*)d_in[1];
    const float* target = (const float*)d_in[2];
    const int*   pm     = (const int*)d_in[3];
    float* out = (float*)d_out;

    static cudaStream_t s1 = nullptr;
    static cudaEvent_t ev0 = nullptr;
    static cudaEvent_t evp[NGRP] = {};
    if (s1 == nullptr) {
        cudaStreamCreateWithFlags(&s1, cudaStreamNonBlocking);
        cudaEventCreateWithFlags(&ev0, cudaEventDisableTiming);
        for (int g = 0; g < NGRP; g++)
            cudaEventCreateWithFlags(&evp[g], cudaEventDisableTiming);
        cudaFuncSetAttribute(k_gemm, cudaFuncAttributeMaxDynamicSharedMemorySize,
                             SMEM_DYN);
    }

    k_init<<<1, 1>>>();
    cudaEventRecord(ev0, 0);
    cudaStreamWaitEvent(s1, ev0, 0);

    // side stream: per-group prep (fuse_tgt + prep_A), event per group
    for (int g = 0; g < NGRP; g++) {
        int b0 = g * GB;
        k_fuse_tgt<<<GB * 512 / 8, 256, 0, s1>>>(target, image, b0);
        k_prep_A<<<(GB * 512 * 96 + 255) / 256, 256, 0, s1>>>(text, b0);
        cudaEventRecord(evp[g], s1);
    }

    // main stream: per-group GEMM, gated on that group's prep
    for (int g = 0; g < NGRP; g++) {
        cudaStreamWaitEvent(0, evp[g], 0);
        k_gemm<<<dim3(16, GB), 256, SMEM_DYN>>>(g * GB);
    }

    k_merge<<<(NROWS + 255) / 256, 256>>>();
    k_rescore<<<512, 256>>>(text, target);
    k_txtloss<<<(NROWS + 7) / 8, 256>>>(text, target, pm);
    k_final<<<(NROWS + 255) / 256, 256>>>(out);
}